// round 8
// baseline (speedup 1.0000x reference)
#include <cuda_runtime.h>
#include <cstdint>
#include <math.h>

#define S_LEN 2048
#define NBATCH 64
#define DIN 512
#define HID 512

// ---------------- helpers ----------------
__device__ __forceinline__ float tf32r(float f) {
    float o; asm("cvt.rna.tf32.f32 %0, %1;" : "=f"(o) : "f"(f)); return o;
}
__device__ __forceinline__ uint32_t f2b(float f) { return __float_as_uint(f); }

__device__ __forceinline__ void mma8(float* c, const uint32_t* a, const uint32_t* b) {
    asm volatile(
        "mma.sync.aligned.m16n8k8.row.col.f32.tf32.tf32.f32 "
        "{%0,%1,%2,%3}, {%4,%5,%6,%7}, {%8,%9}, {%0,%1,%2,%3};"
        : "+f"(c[0]), "+f"(c[1]), "+f"(c[2]), "+f"(c[3])
        : "r"(a[0]), "r"(a[1]), "r"(a[2]), "r"(a[3]), "r"(b[0]), "r"(b[1]));
}
__device__ __forceinline__ float sigm(float x) { return 1.0f / (1.0f + __expf(-x)); }
__device__ __forceinline__ float tanh_f(float x) { return 1.0f - 2.0f / (__expf(2.0f * x) + 1.0f); }

// xp layout: [s][m(64)][r2(32)][b(64)],  r2 = gate*8 + u
__device__ float g_xproj[(size_t)S_LEN * 64 * 32 * 64];
__device__ unsigned int g_bar;
__global__ void reset_bar_kernel() { g_bar = 0u; }

// ================= Phase 1: x_proj = x @ Wih^T + (bih+bhh) =================
// grid (1024, 16); block 256 thr (8 warps: 4 m-warps x 2 n-warps, warp m32 x n64)
// K chunks of 32, double buffered. smem floats:
#define P1_XS0 0
#define P1_XS1 4608          // 128*36
#define P1_WS0 9216
#define P1_WS1 13824
#define P1_BIAS 18432
#define P1_SMEMF 18560
#define P1_SMEM (P1_SMEMF * 4)

__global__ void __launch_bounds__(256, 1)
xproj_kernel(const float* __restrict__ x, const float* __restrict__ Wih,
             const float* __restrict__ bih, const float* __restrict__ bhh)
{
    extern __shared__ float smf[];
    const int tid = threadIdx.x, wid = tid >> 5, lane = tid & 31;
    const int g = lane >> 2, tg = lane & 3;
    const int tt = blockIdx.x, gg = blockIdx.y;
    const int wm = wid & 3, wn = wid >> 2;

    if (tid < 128) smf[P1_BIAS + tid] = bih[gg * 128 + tid] + bhh[gg * 128 + tid];

    const int f4 = tid & 7, row0 = tid >> 3;     // loader role
    float4 rx[4], rw[4];

    // prologue: chunk 0
    #pragma unroll
    for (int p = 0; p < 4; ++p) {
        int r = row0 + p * 32;
        rx[p] = *(const float4*)(x + ((size_t)(tt * 128 + r)) * 512 + f4 * 4);
        rw[p] = *(const float4*)(Wih + ((size_t)(gg * 128 + r)) * 512 + f4 * 4);
    }
    #pragma unroll
    for (int p = 0; p < 4; ++p) {
        int r = row0 + p * 32;
        float4 v = rx[p];
        v.x = tf32r(v.x); v.y = tf32r(v.y); v.z = tf32r(v.z); v.w = tf32r(v.w);
        *(float4*)(smf + P1_XS0 + r * 36 + f4 * 4) = v;
        v = rw[p];
        v.x = tf32r(v.x); v.y = tf32r(v.y); v.z = tf32r(v.z); v.w = tf32r(v.w);
        *(float4*)(smf + P1_WS0 + r * 36 + f4 * 4) = v;
    }
    __syncthreads();

    float acc[2][8][4];
    #pragma unroll
    for (int mt = 0; mt < 2; ++mt)
        #pragma unroll
        for (int nt = 0; nt < 8; ++nt)
            #pragma unroll
            for (int q = 0; q < 4; ++q) acc[mt][nt][q] = 0.0f;

    for (int c = 0; c < 16; ++c) {
        if (c < 15) {
            int kc = (c + 1) * 32;
            #pragma unroll
            for (int p = 0; p < 4; ++p) {
                int r = row0 + p * 32;
                rx[p] = *(const float4*)(x + ((size_t)(tt * 128 + r)) * 512 + kc + f4 * 4);
                rw[p] = *(const float4*)(Wih + ((size_t)(gg * 128 + r)) * 512 + kc + f4 * 4);
            }
        }
        const float* xb = smf + ((c & 1) ? P1_XS1 : P1_XS0);
        const float* wb = smf + ((c & 1) ? P1_WS1 : P1_WS0);
        #pragma unroll
        for (int ks = 0; ks < 4; ++ks) {
            uint32_t afr[2][4], bfr[8][2];
            #pragma unroll
            for (int mt = 0; mt < 2; ++mt) {
                int mrb = wm * 32 + mt * 16;
                afr[mt][0] = f2b(xb[(mrb + g) * 36 + ks * 8 + tg]);
                afr[mt][1] = f2b(xb[(mrb + g + 8) * 36 + ks * 8 + tg]);
                afr[mt][2] = f2b(xb[(mrb + g) * 36 + ks * 8 + tg + 4]);
                afr[mt][3] = f2b(xb[(mrb + g + 8) * 36 + ks * 8 + tg + 4]);
            }
            #pragma unroll
            for (int nt = 0; nt < 8; ++nt) {
                int nb = wn * 64 + nt * 8;
                bfr[nt][0] = f2b(wb[(nb + g) * 36 + ks * 8 + tg]);
                bfr[nt][1] = f2b(wb[(nb + g) * 36 + ks * 8 + tg + 4]);
            }
            #pragma unroll
            for (int mt = 0; mt < 2; ++mt)
                #pragma unroll
                for (int nt = 0; nt < 8; ++nt)
                    mma8(acc[mt][nt], afr[mt], bfr[nt]);
        }
        if (c < 15) {
            float* xd = smf + (((c + 1) & 1) ? P1_XS1 : P1_XS0);
            float* wd = smf + (((c + 1) & 1) ? P1_WS1 : P1_WS0);
            #pragma unroll
            for (int p = 0; p < 4; ++p) {
                int r = row0 + p * 32;
                float4 v = rx[p];
                v.x = tf32r(v.x); v.y = tf32r(v.y); v.z = tf32r(v.z); v.w = tf32r(v.w);
                *(float4*)(xd + r * 36 + f4 * 4) = v;
                v = rw[p];
                v.x = tf32r(v.x); v.y = tf32r(v.y); v.z = tf32r(v.z); v.w = tf32r(v.w);
                *(float4*)(wd + r * 36 + f4 * 4) = v;
            }
        }
        __syncthreads();
    }

    // stage [lt 128][lg 128], pad 133 (conflict-free)
    float* stg = smf;
    #pragma unroll
    for (int mt = 0; mt < 2; ++mt) {
        int ltb = wm * 32 + mt * 16;
        #pragma unroll
        for (int nt = 0; nt < 8; ++nt) {
            int lg = wn * 64 + nt * 8 + tg * 2;
            stg[(ltb + g) * 133 + lg]     = acc[mt][nt][0];
            stg[(ltb + g) * 133 + lg + 1] = acc[mt][nt][1];
            stg[(ltb + g + 8) * 133 + lg]     = acc[mt][nt][2];
            stg[(ltb + g + 8) * 133 + lg + 1] = acc[mt][nt][3];
        }
    }
    __syncthreads();

    // copy-out: chunks (s_l 0..1, m_l 0..15), each contiguous [u8][b64]
    const int gate = gg >> 2;
    const int m0 = (gg & 3) * 16;
    const int s0 = tt * 2;
    #pragma unroll
    for (int rep = 0; rep < 16; ++rep) {
        int lin = rep * 256 + tid;
        int chunk = lin >> 7, within = lin & 127;
        int u = within >> 4, b4 = (within & 15) * 4;
        int s_l = chunk >> 4, m_l = chunk & 15;
        int lg = m_l * 8 + u;
        float bsv = smf[P1_BIAS + lg];
        float4 v;
        v.x = stg[(s_l * 64 + b4 + 0) * 133 + lg] + bsv;
        v.y = stg[(s_l * 64 + b4 + 1) * 133 + lg] + bsv;
        v.z = stg[(s_l * 64 + b4 + 2) * 133 + lg] + bsv;
        v.w = stg[(s_l * 64 + b4 + 3) * 133 + lg] + bsv;
        size_t ob = (((size_t)(s0 + s_l) * 64 + (m0 + m_l)) * 32 + gate * 8 + u) * 64 + b4;
        *(float4*)(g_xproj + ob) = v;
    }
}

// ================= Phase 2: persistent recurrence =================
// 64 blocks x 256 thr (8 warps). Warp kg owns K-slice [kg*64, kg*64+64) and
// computes ALL 32 local gate rows (2 m16 tiles) x 64 batches for that K-slice.
// Block m owns units m*8..m*8+7; local row r2 = gate*8 + u (32 rows).
// smem floats:
#define P2_HK 0                          // hk[kg(8)][b(64)][68]
#define P2_RED 34816                     // red[kg(8)][r2(32)][68]
#define P2_XPT (34816 + 17408)           // xpT[32][68] = 52224
#define P2_SMEMF 54400
#define P2_SMEM (P2_SMEMF * 4)
#define P2_NBLK 64

__global__ void __launch_bounds__(256, 1)
lstm_rec_kernel(const float* __restrict__ Whh, float* __restrict__ out)
{
    extern __shared__ float smf[];
    const int tid = threadIdx.x, wid = tid >> 5, lane = tid & 31;
    const int g = lane >> 2, tg = lane & 3;
    const int m = blockIdx.x;
    const int kg = wid;                    // K-slice owner

    // ---- persistent A fragments: afr[mt][ks][4], rows mt*16 + {g, g+8} ----
    uint32_t afr[2][8][4];
    #pragma unroll
    for (int mt = 0; mt < 2; ++mt) {
        int r2a = mt * 16 + g;
        int G0 = (r2a >> 3) * 512 + m * 8 + (r2a & 7);
        int r2b = r2a + 8;
        int G1 = (r2b >> 3) * 512 + m * 8 + (r2b & 7);
        const float* W0 = Whh + (size_t)G0 * 512 + kg * 64 + tg;
        const float* W1 = Whh + (size_t)G1 * 512 + kg * 64 + tg;
        #pragma unroll
        for (int ks = 0; ks < 8; ++ks) {
            afr[mt][ks][0] = f2b(tf32r(W0[ks * 8]));
            afr[mt][ks][1] = f2b(tf32r(W1[ks * 8]));
            afr[mt][ks][2] = f2b(tf32r(W0[ks * 8 + 4]));
            afr[mt][ks][3] = f2b(tf32r(W1[ks * 8 + 4]));
        }
    }

    float* h_out = out;
    float* c_out = out + (size_t)S_LEN * NBATCH * HID;
    float c_state[2];
    c_state[0] = 0.0f; c_state[1] = 0.0f;
    __syncthreads();

    const int lrow2 = lane >> 4, f4 = lane & 15;   // h-loader role

    for (int s = 0; s < S_LEN; ++s) {
        // xp prefetch -> xpT[r2][b] (pad 68): 512 float4 / 256 thr = 2 each
        #pragma unroll
        for (int rep = 0; rep < 2; ++rep) {
            int i = rep * 256 + tid;
            int r2 = i >> 4, b4 = (i & 15) * 4;
            float4 v = *(const float4*)(g_xproj + (((size_t)s * 64 + m) * 32 + r2) * 64 + b4);
            *(float4*)(smf + P2_XPT + r2 * 68 + b4) = v;
        }

        if (s > 0) {
            // ---- warp kg loads its OWN h slice: all 64 b x 64 k ----
            const float* hbase = h_out + ((size_t)(s - 1) * 64) * 512 + kg * 64;
            #pragma unroll
            for (int rr = 0; rr < 32; ++rr) {
                int b = rr * 2 + lrow2;
                float4 v = *(const float4*)(hbase + (size_t)b * 512 + f4 * 4);
                v.x = tf32r(v.x); v.y = tf32r(v.y); v.z = tf32r(v.z); v.w = tf32r(v.w);
                *(float4*)(smf + P2_HK + (kg * 64 + b) * 68 + f4 * 4) = v;
            }
            __syncwarp();

            // ---- MMA: D[m32, n64] partial over K=64 ----
            float acc[2][8][4];
            #pragma unroll
            for (int mt = 0; mt < 2; ++mt)
                #pragma unroll
                for (int nt = 0; nt < 8; ++nt)
                    #pragma unroll
                    for (int q = 0; q < 4; ++q) acc[mt][nt][q] = 0.0f;

            const float* hkb = smf + P2_HK + kg * 64 * 68;
            #pragma unroll
            for (int ks = 0; ks < 8; ++ks) {
                uint32_t bfr[8][2];
                #pragma unroll
                for (int nt = 0; nt < 8; ++nt) {
                    bfr[nt][0] = f2b(hkb[(nt * 8 + g) * 68 + ks * 8 + tg]);
                    bfr[nt][1] = f2b(hkb[(nt * 8 + g) * 68 + ks * 8 + tg + 4]);
                }
                #pragma unroll
                for (int mt = 0; mt < 2; ++mt)
                    #pragma unroll
                    for (int nt = 0; nt < 8; ++nt)
                        mma8(acc[mt][nt], afr[mt][ks], bfr[nt]);
            }
            // ---- store partials: red[kg][r2][68] ----
            float* rw = smf + P2_RED + kg * 32 * 68;
            #pragma unroll
            for (int mt = 0; mt < 2; ++mt)
                #pragma unroll
                for (int nt = 0; nt < 8; ++nt) {
                    int col = nt * 8 + tg * 2;
                    rw[(mt * 16 + g) * 68 + col]     = acc[mt][nt][0];
                    rw[(mt * 16 + g) * 68 + col + 1] = acc[mt][nt][1];
                    rw[(mt * 16 + g + 8) * 68 + col]     = acc[mt][nt][2];
                    rw[(mt * 16 + g + 8) * 68 + col + 1] = acc[mt][nt][3];
                }
        }
        __syncthreads();

        // ---- reduce 8 kg partials + xp -> xpT in place: 512 f4 / 256 thr ----
        #pragma unroll
        for (int rep = 0; rep < 2; ++rep) {
            int i = rep * 256 + tid;
            int r = i >> 4, bq = (i & 15) * 4;
            float4 v = *(float4*)(smf + P2_XPT + r * 68 + bq);
            if (s > 0) {
                #pragma unroll
                for (int k2 = 0; k2 < 8; ++k2) {
                    float4 p = *(float4*)(smf + P2_RED + (k2 * 32 + r) * 68 + bq);
                    v.x += p.x; v.y += p.y; v.z += p.z; v.w += p.w;
                }
            }
            *(float4*)(smf + P2_XPT + r * 68 + bq) = v;
        }
        __syncthreads();

        // ---- cell: thread (u = tid&7, b = tid>>3 and +32) ----
        {
            int u = tid & 7;
            #pragma unroll
            for (int half = 0; half < 2; ++half) {
                int b = (tid >> 3) + half * 32;
                float iv = smf[P2_XPT + (0 * 8 + u) * 68 + b];
                float fv = smf[P2_XPT + (1 * 8 + u) * 68 + b];
                float gv = smf[P2_XPT + (2 * 8 + u) * 68 + b];
                float ov = smf[P2_XPT + (3 * 8 + u) * 68 + b];
                float cv = sigm(fv) * c_state[half] + sigm(iv) * tanh_f(gv);
                c_state[half] = cv;
                float hv = sigm(ov) * tanh_f(cv);
                size_t o = ((size_t)s * 64 + b) * 512 + m * 8 + u;
                h_out[o] = hv;
                c_out[o] = cv;
            }
        }
        __syncthreads();
        if (tid == 0) {
            __threadfence();
            atomicAdd(&g_bar, 1u);
            unsigned tgt = (unsigned)P2_NBLK * (unsigned)(s + 1);
            while (*((volatile unsigned int*)&g_bar) < tgt) { }
            __threadfence();
        }
        __syncthreads();
    }
}

extern "C" void kernel_launch(void* const* d_in, const int* in_sizes, int n_in,
                              void* d_out, int out_size)
{
    (void)in_sizes; (void)n_in; (void)out_size;
    const float* x   = (const float*)d_in[0];
    const float* Wih = (const float*)d_in[1];
    const float* Whh = (const float*)d_in[2];
    const float* bih = (const float*)d_in[3];
    const float* bhh = (const float*)d_in[4];
    float* out = (float*)d_out;

    static int once = 0;
    if (!once) {
        cudaFuncSetAttribute(xproj_kernel, cudaFuncAttributeMaxDynamicSharedMemorySize, P1_SMEM);
        cudaFuncSetAttribute(lstm_rec_kernel, cudaFuncAttributeMaxDynamicSharedMemorySize, P2_SMEM);
        once = 1;
    }
    reset_bar_kernel<<<1, 1>>>();
    xproj_kernel<<<dim3(1024, 16), 256, P1_SMEM>>>(x, Wih, bih, bhh);
    lstm_rec_kernel<<<P2_NBLK, 256, P2_SMEM>>>(Whh, out);
}

// round 9
// speedup vs baseline: 1.1848x; 1.1848x over previous
#include <cuda_runtime.h>
#include <cstdint>
#include <math.h>

#define S_LEN 2048
#define NBATCH 64
#define DIN 512
#define HID 512

// ---------------- helpers ----------------
__device__ __forceinline__ float tf32r(float f) {
    float o; asm("cvt.rna.tf32.f32 %0, %1;" : "=f"(o) : "f"(f)); return o;
}
__device__ __forceinline__ uint32_t f2b(float f) { return __float_as_uint(f); }

__device__ __forceinline__ void mma8(float* c, const uint32_t* a, const uint32_t* b) {
    asm volatile(
        "mma.sync.aligned.m16n8k8.row.col.f32.tf32.tf32.f32 "
        "{%0,%1,%2,%3}, {%4,%5,%6,%7}, {%8,%9}, {%0,%1,%2,%3};"
        : "+f"(c[0]), "+f"(c[1]), "+f"(c[2]), "+f"(c[3])
        : "r"(a[0]), "r"(a[1]), "r"(a[2]), "r"(a[3]), "r"(b[0]), "r"(b[1]));
}
__device__ __forceinline__ float sigm(float x) { return 1.0f / (1.0f + __expf(-x)); }
__device__ __forceinline__ float tanh_f(float x) { return 1.0f - 2.0f / (__expf(2.0f * x) + 1.0f); }

// xp layout: [s][m(64)][r2(32)][b(64)],  r2 = gate*8 + u
__device__ float g_xproj[(size_t)S_LEN * 64 * 32 * 64];
__device__ unsigned int g_bar;

// ================= Phase 1: x_proj = x @ Wih^T + (bih+bhh) =================
// grid (16, 1024): gg = blockIdx.x (gate tile), tt = blockIdx.y (token tile).
// Consecutive blocks share the x tile -> x read once from DRAM.
// block 256 thr (8 warps: 4 m-warps x 2 n-warps, warp m32 x n64)
#define P1_XS0 0
#define P1_XS1 4608          // 128*36
#define P1_WS0 9216
#define P1_WS1 13824
#define P1_BIAS 18432
#define P1_SMEMF 18560
#define P1_SMEM (P1_SMEMF * 4)

__global__ void __launch_bounds__(256, 1)
xproj_kernel(const float* __restrict__ x, const float* __restrict__ Wih,
             const float* __restrict__ bih, const float* __restrict__ bhh)
{
    extern __shared__ float smf[];
    const int tid = threadIdx.x, wid = tid >> 5, lane = tid & 31;
    const int g = lane >> 2, tg = lane & 3;
    const int gg = blockIdx.x, tt = blockIdx.y;
    const int wm = wid & 3, wn = wid >> 2;

    // reset phase-2 grid barrier (stream-ordered before lstm_rec launch)
    if (gg == 0 && tt == 0 && tid == 0) g_bar = 0u;

    if (tid < 128) smf[P1_BIAS + tid] = bih[gg * 128 + tid] + bhh[gg * 128 + tid];

    const int f4 = tid & 7, row0 = tid >> 3;     // loader role
    float4 rx[4], rw[4];

    // prologue: chunk 0
    #pragma unroll
    for (int p = 0; p < 4; ++p) {
        int r = row0 + p * 32;
        rx[p] = *(const float4*)(x + ((size_t)(tt * 128 + r)) * 512 + f4 * 4);
        rw[p] = *(const float4*)(Wih + ((size_t)(gg * 128 + r)) * 512 + f4 * 4);
    }
    #pragma unroll
    for (int p = 0; p < 4; ++p) {
        int r = row0 + p * 32;
        float4 v = rx[p];
        v.x = tf32r(v.x); v.y = tf32r(v.y); v.z = tf32r(v.z); v.w = tf32r(v.w);
        *(float4*)(smf + P1_XS0 + r * 36 + f4 * 4) = v;
        v = rw[p];
        v.x = tf32r(v.x); v.y = tf32r(v.y); v.z = tf32r(v.z); v.w = tf32r(v.w);
        *(float4*)(smf + P1_WS0 + r * 36 + f4 * 4) = v;
    }
    __syncthreads();

    float acc[2][8][4];
    #pragma unroll
    for (int mt = 0; mt < 2; ++mt)
        #pragma unroll
        for (int nt = 0; nt < 8; ++nt)
            #pragma unroll
            for (int q = 0; q < 4; ++q) acc[mt][nt][q] = 0.0f;

    for (int c = 0; c < 16; ++c) {
        if (c < 15) {
            int kc = (c + 1) * 32;
            #pragma unroll
            for (int p = 0; p < 4; ++p) {
                int r = row0 + p * 32;
                rx[p] = *(const float4*)(x + ((size_t)(tt * 128 + r)) * 512 + kc + f4 * 4);
                rw[p] = *(const float4*)(Wih + ((size_t)(gg * 128 + r)) * 512 + kc + f4 * 4);
            }
        }
        const float* xb = smf + ((c & 1) ? P1_XS1 : P1_XS0);
        const float* wb = smf + ((c & 1) ? P1_WS1 : P1_WS0);
        #pragma unroll
        for (int ks = 0; ks < 4; ++ks) {
            uint32_t afr[2][4], bfr[8][2];
            #pragma unroll
            for (int mt = 0; mt < 2; ++mt) {
                int mrb = wm * 32 + mt * 16;
                afr[mt][0] = f2b(xb[(mrb + g) * 36 + ks * 8 + tg]);
                afr[mt][1] = f2b(xb[(mrb + g + 8) * 36 + ks * 8 + tg]);
                afr[mt][2] = f2b(xb[(mrb + g) * 36 + ks * 8 + tg + 4]);
                afr[mt][3] = f2b(xb[(mrb + g + 8) * 36 + ks * 8 + tg + 4]);
            }
            #pragma unroll
            for (int nt = 0; nt < 8; ++nt) {
                int nb = wn * 64 + nt * 8;
                bfr[nt][0] = f2b(wb[(nb + g) * 36 + ks * 8 + tg]);
                bfr[nt][1] = f2b(wb[(nb + g) * 36 + ks * 8 + tg + 4]);
            }
            #pragma unroll
            for (int mt = 0; mt < 2; ++mt)
                #pragma unroll
                for (int nt = 0; nt < 8; ++nt)
                    mma8(acc[mt][nt], afr[mt], bfr[nt]);
        }
        if (c < 15) {
            float* xd = smf + (((c + 1) & 1) ? P1_XS1 : P1_XS0);
            float* wd = smf + (((c + 1) & 1) ? P1_WS1 : P1_WS0);
            #pragma unroll
            for (int p = 0; p < 4; ++p) {
                int r = row0 + p * 32;
                float4 v = rx[p];
                v.x = tf32r(v.x); v.y = tf32r(v.y); v.z = tf32r(v.z); v.w = tf32r(v.w);
                *(float4*)(xd + r * 36 + f4 * 4) = v;
                v = rw[p];
                v.x = tf32r(v.x); v.y = tf32r(v.y); v.z = tf32r(v.z); v.w = tf32r(v.w);
                *(float4*)(wd + r * 36 + f4 * 4) = v;
            }
        }
        __syncthreads();
    }

    // stage [lt 128][lg 128], pad 133 (conflict-free)
    float* stg = smf;
    #pragma unroll
    for (int mt = 0; mt < 2; ++mt) {
        int ltb = wm * 32 + mt * 16;
        #pragma unroll
        for (int nt = 0; nt < 8; ++nt) {
            int lg = wn * 64 + nt * 8 + tg * 2;
            stg[(ltb + g) * 133 + lg]     = acc[mt][nt][0];
            stg[(ltb + g) * 133 + lg + 1] = acc[mt][nt][1];
            stg[(ltb + g + 8) * 133 + lg]     = acc[mt][nt][2];
            stg[(ltb + g + 8) * 133 + lg + 1] = acc[mt][nt][3];
        }
    }
    __syncthreads();

    // copy-out: chunks (s_l 0..1, m_l 0..15), each contiguous [u8][b64]
    const int gate = gg >> 2;
    const int m0 = (gg & 3) * 16;
    const int s0 = tt * 2;
    #pragma unroll
    for (int rep = 0; rep < 16; ++rep) {
        int lin = rep * 256 + tid;
        int chunk = lin >> 7, within = lin & 127;
        int u = within >> 4, b4 = (within & 15) * 4;
        int s_l = chunk >> 4, m_l = chunk & 15;
        int lg = m_l * 8 + u;
        float bsv = smf[P1_BIAS + lg];
        float4 v;
        v.x = stg[(s_l * 64 + b4 + 0) * 133 + lg] + bsv;
        v.y = stg[(s_l * 64 + b4 + 1) * 133 + lg] + bsv;
        v.z = stg[(s_l * 64 + b4 + 2) * 133 + lg] + bsv;
        v.w = stg[(s_l * 64 + b4 + 3) * 133 + lg] + bsv;
        size_t ob = (((size_t)(s0 + s_l) * 64 + (m0 + m_l)) * 32 + gate * 8 + u) * 64 + b4;
        *(float4*)(g_xproj + ob) = v;
    }
}

// ================= Phase 2: persistent recurrence =================
// 64 blocks x 512 thr (16 warps: kg = wid>>1 (K-slice of 64), nh = wid&1
// (batch half of 32)). Warp (kg,nh) loads exactly its own h slice and computes
// D[m32, n32] partial. Block m owns units m*8..m*8+7; r2 = gate*8 + u.
// smem floats:
#define P2_HK 0                          // hk[16 warp][32 b_local][68]
#define P2_RED 34816                     // red[kg(8)][r2(32)][68]
#define P2_XPT 52224                     // xpT[32][68]
#define P2_SMEMF 54400
#define P2_SMEM (P2_SMEMF * 4)
#define P2_NBLK 64

__global__ void __launch_bounds__(512, 1)
lstm_rec_kernel(const float* __restrict__ Whh, float* __restrict__ out)
{
    extern __shared__ float smf[];
    const int tid = threadIdx.x, wid = tid >> 5, lane = tid & 31;
    const int g = lane >> 2, tg = lane & 3;
    const int m = blockIdx.x;
    const int kg = wid >> 1;               // K-slice 0..7
    const int nh = wid & 1;                // batch half 0..1

    // ---- persistent A fragments: afr[mt][ks][4], rows mt*16 + {g, g+8} ----
    uint32_t afr[2][8][4];
    #pragma unroll
    for (int mt = 0; mt < 2; ++mt) {
        int r2a = mt * 16 + g;
        int G0 = (r2a >> 3) * 512 + m * 8 + (r2a & 7);
        int r2b = r2a + 8;
        int G1 = (r2b >> 3) * 512 + m * 8 + (r2b & 7);
        const float* W0 = Whh + (size_t)G0 * 512 + kg * 64 + tg;
        const float* W1 = Whh + (size_t)G1 * 512 + kg * 64 + tg;
        #pragma unroll
        for (int ks = 0; ks < 8; ++ks) {
            afr[mt][ks][0] = f2b(tf32r(W0[ks * 8]));
            afr[mt][ks][1] = f2b(tf32r(W1[ks * 8]));
            afr[mt][ks][2] = f2b(tf32r(W0[ks * 8 + 4]));
            afr[mt][ks][3] = f2b(tf32r(W1[ks * 8 + 4]));
        }
    }

    float* h_out = out;
    float* c_out = out + (size_t)S_LEN * NBATCH * HID;
    float c_state = 0.0f;                  // thread (u = tid&7, b = tid>>3)
    __syncthreads();

    const int lrow2 = lane >> 4, f4 = lane & 15;   // h-loader role
    float* hk_w = smf + P2_HK + wid * (32 * 68);

    for (int s = 0; s < S_LEN; ++s) {
        // xp prefetch -> xpT[r2][b] (pad 68): 512 float4 / 512 thr
        {
            int r2 = tid >> 4, b4 = (tid & 15) * 4;
            float4 v = *(const float4*)(g_xproj + (((size_t)s * 64 + m) * 32 + r2) * 64 + b4);
            *(float4*)(smf + P2_XPT + r2 * 68 + b4) = v;
        }

        if (s > 0) {
            // ---- warp (kg,nh) loads its OWN h slice: 32 b x 64 k = 8 KB ----
            const float* hbase = h_out + ((size_t)(s - 1) * 64 + nh * 32) * 512 + kg * 64;
            #pragma unroll
            for (int rr = 0; rr < 16; ++rr) {
                int bl = rr * 2 + lrow2;
                float4 v = *(const float4*)(hbase + (size_t)bl * 512 + f4 * 4);
                v.x = tf32r(v.x); v.y = tf32r(v.y); v.z = tf32r(v.z); v.w = tf32r(v.w);
                *(float4*)(hk_w + bl * 68 + f4 * 4) = v;
            }
            __syncwarp();

            // ---- MMA: D[m32, n32] partial over K=64 ----
            float acc[2][4][4];
            #pragma unroll
            for (int mt = 0; mt < 2; ++mt)
                #pragma unroll
                for (int nt = 0; nt < 4; ++nt)
                    #pragma unroll
                    for (int q = 0; q < 4; ++q) acc[mt][nt][q] = 0.0f;

            #pragma unroll
            for (int ks = 0; ks < 8; ++ks) {
                uint32_t bfr[4][2];
                #pragma unroll
                for (int nt = 0; nt < 4; ++nt) {
                    bfr[nt][0] = f2b(hk_w[(nt * 8 + g) * 68 + ks * 8 + tg]);
                    bfr[nt][1] = f2b(hk_w[(nt * 8 + g) * 68 + ks * 8 + tg + 4]);
                }
                #pragma unroll
                for (int mt = 0; mt < 2; ++mt)
                    #pragma unroll
                    for (int nt = 0; nt < 4; ++nt)
                        mma8(acc[mt][nt], afr[mt][ks], bfr[nt]);
            }
            // ---- store partials: red[kg][r2][b], b = nh*32 + col ----
            float* rw = smf + P2_RED + kg * (32 * 68);
            #pragma unroll
            for (int mt = 0; mt < 2; ++mt)
                #pragma unroll
                for (int nt = 0; nt < 4; ++nt) {
                    int col = nh * 32 + nt * 8 + tg * 2;
                    rw[(mt * 16 + g) * 68 + col]     = acc[mt][nt][0];
                    rw[(mt * 16 + g) * 68 + col + 1] = acc[mt][nt][1];
                    rw[(mt * 16 + g + 8) * 68 + col]     = acc[mt][nt][2];
                    rw[(mt * 16 + g + 8) * 68 + col + 1] = acc[mt][nt][3];
                }
        }
        __syncthreads();

        // ---- fused reduce + cell: thread (u = tid&7, b = tid>>3) ----
        {
            int u = tid & 7, b = tid >> 3;
            float gate[4];
            #pragma unroll
            for (int g4 = 0; g4 < 4; ++g4) {
                int r2 = g4 * 8 + u;
                float v = smf[P2_XPT + r2 * 68 + b];
                if (s > 0) {
                    #pragma unroll
                    for (int k2 = 0; k2 < 8; ++k2)
                        v += smf[P2_RED + k2 * (32 * 68) + r2 * 68 + b];
                }
                gate[g4] = v;
            }
            float cv = sigm(gate[1]) * c_state + sigm(gate[0]) * tanh_f(gate[2]);
            c_state = cv;
            float hv = sigm(gate[3]) * tanh_f(cv);
            size_t o = ((size_t)s * 64 + b) * 512 + m * 8 + u;
            h_out[o] = hv;
            c_out[o] = cv;
        }
        __syncthreads();

        // ---- grid barrier (acq/rel, no L1 flush) ----
        if (tid == 0) {
            asm volatile("red.release.gpu.global.add.u32 [%0], 1;"
                         :: "l"(&g_bar) : "memory");
            unsigned tgt = (unsigned)P2_NBLK * (unsigned)(s + 1);
            unsigned cur;
            do {
                asm volatile("ld.acquire.gpu.global.u32 %0, [%1];"
                             : "=r"(cur) : "l"(&g_bar) : "memory");
            } while (cur < tgt);
        }
        __syncthreads();
    }
}

extern "C" void kernel_launch(void* const* d_in, const int* in_sizes, int n_in,
                              void* d_out, int out_size)
{
    (void)in_sizes; (void)n_in; (void)out_size;
    const float* x   = (const float*)d_in[0];
    const float* Wih = (const float*)d_in[1];
    const float* Whh = (const float*)d_in[2];
    const float* bih = (const float*)d_in[3];
    const float* bhh = (const float*)d_in[4];
    float* out = (float*)d_out;

    static int once = 0;
    if (!once) {
        cudaFuncSetAttribute(xproj_kernel, cudaFuncAttributeMaxDynamicSharedMemorySize, P1_SMEM);
        cudaFuncSetAttribute(lstm_rec_kernel, cudaFuncAttributeMaxDynamicSharedMemorySize, P2_SMEM);
        once = 1;
    }
    xproj_kernel<<<dim3(16, 1024), 256, P1_SMEM>>>(x, Wih, bih, bhh);
    lstm_rec_kernel<<<P2_NBLK, 512, P2_SMEM>>>(Whh, out);
}